// round 4
// baseline (speedup 1.0000x reference)
#include <cuda_runtime.h>

// ---------------------------------------------------------------------------
// Signed 3-layer GCN + mean-pool + LayerNorm, restructured as:
//   per layer: z_pos/z_neg = (A_sign + selfdiag) @ h   (one edge pass, CSR by dst)
//              h' = relu(z_pos@Wp + bp) - relu(z_neg@Wn + bn)   (two SGEMMs)
// Preprocessing (per call, deterministic): degree count -> scan -> CSR scatter.
// NOTE: edge_index / batch are int32 (JAX x64 disabled downcasts int64->int32).
// ---------------------------------------------------------------------------

#define DD    128
#define MAXN  100352            // 784 * 128, padded node capacity
#define MAXE  3200000
#define MAXG  64
#define EPSLN 1e-5f

__device__ float g_zpos[(size_t)MAXN * DD];
__device__ float g_zneg[(size_t)MAXN * DD];
__device__ float g_hA  [(size_t)MAXN * DD];
__device__ float g_hB  [(size_t)MAXN * DD];
__device__ int   g_esrc [MAXE];
__device__ float g_ecoef[MAXE];
__device__ int   g_rowptr[MAXN + 1];
__device__ int   g_cntp[MAXN];
__device__ int   g_cntn[MAXN];
__device__ int   g_cursor[MAXN];
__device__ int   g_cntall[MAXN];
__device__ float g_dinvp[MAXN];
__device__ float g_dinvn[MAXN];
__device__ float g_selfp[MAXN];
__device__ float g_selfn[MAXN];
__device__ int   g_bsum[256];
__device__ int   g_boff[256];
__device__ float g_pool[MAXG * DD];
__device__ int   g_pcnt[MAXG];

__device__ __forceinline__ float* hbuf(int s) { return s == 0 ? g_hA : g_hB; }
__device__ __forceinline__ int clampi(int v, int hi) {   // [0, hi)
    return v < 0 ? 0 : (v >= hi ? hi - 1 : v);
}

// ---------------------------------------------------------------- init
__global__ void k_init(int N) {
    int i = blockIdx.x * blockDim.x + threadIdx.x;
    if (i < N) { g_cntp[i] = 0; g_cntn[i] = 0; g_cursor[i] = 0; }
    if (i < MAXG * DD) g_pool[i] = 0.f;
    if (i < MAXG) g_pcnt[i] = 0;
}

// ---------------------------------------------------------------- degree count
__global__ void k_degree(const int* __restrict__ ei,
                         const float* __restrict__ ew, int E, int N) {
    int e = blockIdx.x * blockDim.x + threadIdx.x;
    if (e >= E) return;
    int dst = clampi(ei[E + e], N);
    float w = ew[e];
    if (w > 0.f)      atomicAdd(&g_cntp[dst], 1);
    else if (w < 0.f) atomicAdd(&g_cntn[dst], 1);
}

// ---------------------------------------------------------------- node params
__global__ void k_nodeparams(int N) {
    int v = blockIdx.x * blockDim.x + threadIdx.x;
    if (v >= N) return;
    int cp = g_cntp[v], cn = g_cntn[v];
    float dp = 1.f + (float)cp;
    float dn = 1.f + (float)cn;
    g_dinvp[v] = rsqrtf(dp);
    g_dinvn[v] = rsqrtf(dn);
    g_selfp[v] = 1.f / dp;
    g_selfn[v] = 1.f / dn;
    g_cntall[v] = cp + cn;
}

// ---------------------------------------------------------------- scan stage 1
__global__ void k_scan1(int N) {
    __shared__ int sm[32];
    int i = blockIdx.x * 1024 + threadIdx.x;
    int v = (i < N) ? g_cntall[i] : 0;
    int lane = threadIdx.x & 31, w = threadIdx.x >> 5;
    #pragma unroll
    for (int o = 16; o > 0; o >>= 1) v += __shfl_down_sync(0xffffffffu, v, o);
    if (lane == 0) sm[w] = v;
    __syncthreads();
    if (w == 0) {
        int t = sm[lane];
        #pragma unroll
        for (int o = 16; o > 0; o >>= 1) t += __shfl_down_sync(0xffffffffu, t, o);
        if (lane == 0) g_bsum[blockIdx.x] = t;
    }
}

// ---------------------------------------------------------------- scan stage 2
__global__ void k_scan2(int nb, int N) {
    if (threadIdx.x == 0 && blockIdx.x == 0) {
        int run = 0;
        for (int b = 0; b < nb; b++) { g_boff[b] = run; run += g_bsum[b]; }
        g_rowptr[N] = run;
    }
}

// ---------------------------------------------------------------- scan stage 3
__global__ void k_scan3(int N) {
    __shared__ int ws[32];
    int i = blockIdx.x * 1024 + threadIdx.x;
    int v = (i < N) ? g_cntall[i] : 0;
    int lane = threadIdx.x & 31, w = threadIdx.x >> 5;
    int x = v;
    #pragma unroll
    for (int o = 1; o < 32; o <<= 1) {
        int y = __shfl_up_sync(0xffffffffu, x, o);
        if (lane >= o) x += y;
    }
    if (lane == 31) ws[w] = x;
    __syncthreads();
    if (threadIdx.x < 32) {
        int t = ws[threadIdx.x];
        int y = t;
        #pragma unroll
        for (int o = 1; o < 32; o <<= 1) {
            int z = __shfl_up_sync(0xffffffffu, y, o);
            if (threadIdx.x >= o) y += z;
        }
        ws[threadIdx.x] = y - t;   // exclusive warp offset
    }
    __syncthreads();
    if (i < N) g_rowptr[i] = (x - v) + ws[w] + g_boff[blockIdx.x];
}

// ---------------------------------------------------------------- CSR scatter
__global__ void k_scatter(const int* __restrict__ ei,
                          const float* __restrict__ ew, int E, int N) {
    int e = blockIdx.x * blockDim.x + threadIdx.x;
    if (e >= E) return;
    float w = ew[e];
    if (w == 0.f) return;
    int s = clampi(ei[e], N);
    int d = clampi(ei[E + e], N);
    int pos = g_rowptr[d] + atomicAdd(&g_cursor[d], 1);
    float c;
    if (w > 0.f) c =  g_dinvp[s] * g_dinvp[d];
    else         c = -(g_dinvn[s] * g_dinvn[d]);
    g_esrc[pos]  = s;
    g_ecoef[pos] = c;
}

// ---------------------------------------------------------------- aggregation
// one warp per destination node; lane = 4 consecutive columns (float4)
// insel: -1 = external x, 0 = g_hA, 1 = g_hB
__global__ void __launch_bounds__(256) k_agg(const float* __restrict__ x,
                                             int insel, int N) {
    const float* h = (insel < 0) ? x : hbuf(insel);
    int gw   = (blockIdx.x * blockDim.x + threadIdx.x) >> 5;
    int lane = threadIdx.x & 31;
    if (gw >= N) return;
    int v = gw;
    int beg = g_rowptr[v], end = g_rowptr[v + 1];

    float4 aP = make_float4(0.f, 0.f, 0.f, 0.f);
    float4 aN = make_float4(0.f, 0.f, 0.f, 0.f);

    for (int base = beg; base < end; base += 32) {
        int idx = base + lane;
        int s = 0; float c = 0.f;
        if (idx < end) { s = g_esrc[idx]; c = g_ecoef[idx]; }
        int cnt = min(32, end - base);
        for (int j = 0; j < cnt; j++) {
            int   sj = __shfl_sync(0xffffffffu, s, j);
            float cj = __shfl_sync(0xffffffffu, c, j);
            float4 hv = __ldg(((const float4*)(h + (size_t)sj * DD)) + lane);
            if (cj > 0.f) {
                aP.x += cj * hv.x; aP.y += cj * hv.y;
                aP.z += cj * hv.z; aP.w += cj * hv.w;
            } else {
                float m = -cj;
                aN.x += m * hv.x; aN.y += m * hv.y;
                aN.z += m * hv.z; aN.w += m * hv.w;
            }
        }
    }
    // self-loop terms
    float4 hv = __ldg(((const float4*)(h + (size_t)v * DD)) + lane);
    float sp = g_selfp[v], sn = g_selfn[v];
    aP.x += sp * hv.x; aP.y += sp * hv.y; aP.z += sp * hv.z; aP.w += sp * hv.w;
    aN.x += sn * hv.x; aN.y += sn * hv.y; aN.z += sn * hv.z; aN.w += sn * hv.w;

    ((float4*)(g_zpos + (size_t)v * DD))[lane] = aP;
    ((float4*)(g_zneg + (size_t)v * DD))[lane] = aN;
}

// ---------------------------------------------------------------- SGEMM
// asel: 0 = g_zpos, 1 = g_zneg.  outsel: 0 = g_hA, 1 = g_hB.
// sub=0: out = relu(A@W + b);  sub=1: out -= relu(A@W + b)
// 256 thr, 128x128 tile, 8x8 microtile
__global__ void __launch_bounds__(256) k_gemm(int asel,
                                              const float* __restrict__ W,
                                              const float* __restrict__ bias,
                                              int outsel, int sub) {
    const float* A = (asel == 0) ? g_zpos : g_zneg;
    float* out = hbuf(outsel);

    __shared__ float As[8 * 128];
    __shared__ float Bs[8 * 128];
    int tid = threadIdx.x;
    const int blockM = blockIdx.x * 128;
    int arow = tid >> 1, acol = (tid & 1) * 4;
    int brow = tid >> 5, bcol = (tid & 31) * 4;
    int ty = tid >> 4, tx = tid & 15;

    float acc[8][8] = {};

    for (int k0 = 0; k0 < 128; k0 += 8) {
        float4 av = *(const float4*)(A + (size_t)(blockM + arow) * 128 + k0 + acol);
        As[(acol + 0) * 128 + arow] = av.x;
        As[(acol + 1) * 128 + arow] = av.y;
        As[(acol + 2) * 128 + arow] = av.z;
        As[(acol + 3) * 128 + arow] = av.w;
        *(float4*)&Bs[brow * 128 + bcol] =
            *(const float4*)(W + (size_t)(k0 + brow) * 128 + bcol);
        __syncthreads();
        #pragma unroll
        for (int k = 0; k < 8; k++) {
            float4 a0 = *(float4*)&As[k * 128 + ty * 8];
            float4 a1 = *(float4*)&As[k * 128 + ty * 8 + 4];
            float4 b0 = *(float4*)&Bs[k * 128 + tx * 8];
            float4 b1 = *(float4*)&Bs[k * 128 + tx * 8 + 4];
            float ra[8] = {a0.x, a0.y, a0.z, a0.w, a1.x, a1.y, a1.z, a1.w};
            float rb[8] = {b0.x, b0.y, b0.z, b0.w, b1.x, b1.y, b1.z, b1.w};
            #pragma unroll
            for (int i = 0; i < 8; i++)
                #pragma unroll
                for (int j = 0; j < 8; j++)
                    acc[i][j] += ra[i] * rb[j];
        }
        __syncthreads();
    }

    float bb[8];
    #pragma unroll
    for (int j = 0; j < 8; j++) bb[j] = __ldg(bias + tx * 8 + j);

    #pragma unroll
    for (int i = 0; i < 8; i++) {
        size_t gr = (size_t)(blockM + ty * 8 + i);
        float* orow = out + gr * 128 + tx * 8;
        #pragma unroll
        for (int jj = 0; jj < 8; jj += 4) {
            float4 r;
            r.x = fmaxf(acc[i][jj + 0] + bb[jj + 0], 0.f);
            r.y = fmaxf(acc[i][jj + 1] + bb[jj + 1], 0.f);
            r.z = fmaxf(acc[i][jj + 2] + bb[jj + 2], 0.f);
            r.w = fmaxf(acc[i][jj + 3] + bb[jj + 3], 0.f);
            if (sub) {
                float4 o = *(float4*)(orow + jj);
                o.x -= r.x; o.y -= r.y; o.z -= r.z; o.w -= r.w;
                *(float4*)(orow + jj) = o;
            } else {
                *(float4*)(orow + jj) = r;
            }
        }
    }
}

// ---------------------------------------------------------------- mean pool
// block = 128 threads (one per column), processes 128 contiguous nodes;
// batch is sorted, so runs are accumulated locally and flushed on change.
__global__ void k_pool(int insel, const int* __restrict__ batch, int N, int G) {
    const float* h = hbuf(insel);
    int t = threadIdx.x;
    int v0 = blockIdx.x * 128;
    int vend = min(v0 + 128, N);
    float acc = 0.f;
    int curg = -1, cnt = 0;
    for (int v = v0; v < vend; v++) {
        int g = clampi(batch[v], G);
        if (g != curg) {
            if (curg >= 0) {
                atomicAdd(&g_pool[curg * DD + t], acc);
                if (t == 0) atomicAdd(&g_pcnt[curg], cnt);
            }
            curg = g; acc = 0.f; cnt = 0;
        }
        acc += h[(size_t)v * DD + t];
        cnt++;
    }
    if (curg >= 0) {
        atomicAdd(&g_pool[curg * DD + t], acc);
        if (t == 0) atomicAdd(&g_pcnt[curg], cnt);
    }
}

// ---------------------------------------------------------------- layernorm
__global__ void k_ln(const float* __restrict__ gamma,
                     const float* __restrict__ beta,
                     float* __restrict__ out) {
    __shared__ float sm[4];
    int g = blockIdx.x, t = threadIdx.x;
    int lane = t & 31, w = t >> 5;
    float cnt = fmaxf((float)g_pcnt[g], 1.f);
    float v = g_pool[g * DD + t] / cnt;

    float s = v;
    #pragma unroll
    for (int o = 16; o > 0; o >>= 1) s += __shfl_xor_sync(0xffffffffu, s, o);
    if (lane == 0) sm[w] = s;
    __syncthreads();
    float mu = (sm[0] + sm[1] + sm[2] + sm[3]) * (1.f / 128.f);
    __syncthreads();

    float d = v - mu;
    float s2 = d * d;
    #pragma unroll
    for (int o = 16; o > 0; o >>= 1) s2 += __shfl_xor_sync(0xffffffffu, s2, o);
    if (lane == 0) sm[w] = s2;
    __syncthreads();
    float var = (sm[0] + sm[1] + sm[2] + sm[3]) * (1.f / 128.f);

    out[g * DD + t] = d * rsqrtf(var + EPSLN) * gamma[t] + beta[t];
}

// ---------------------------------------------------------------- launch
extern "C" void kernel_launch(void* const* d_in, const int* in_sizes, int n_in,
                              void* d_out, int out_size) {
    const float* x     = (const float*)d_in[0];
    const int*   ei    = (const int*)d_in[1];
    const float* ew    = (const float*)d_in[2];
    const int*   batch = (const int*)d_in[3];
    const float* Wp    = (const float*)d_in[4];
    const float* bp    = (const float*)d_in[5];
    const float* Wn    = (const float*)d_in[6];
    const float* bn    = (const float*)d_in[7];
    const float* gamma = (const float*)d_in[8];
    const float* beta  = (const float*)d_in[9];

    int N = in_sizes[0] / DD;
    int E = in_sizes[1] / 2;
    int L = in_sizes[4] / (DD * DD);
    int G = out_size / DD;

    int nbN  = (N + 255) / 256;
    int nbE  = (E + 255) / 256;
    int nbSc = (N + 1023) / 1024;
    int nbAg = (N * 32 + 255) / 256;      // one warp per node
    int nbGm = (N + 127) / 128;           // 128-row GEMM tiles
    int nbPl = (N + 127) / 128;

    // preprocessing (per call; deterministic structure)
    k_init<<<nbN, 256>>>(N);
    k_degree<<<nbE, 256>>>(ei, ew, E, N);
    k_nodeparams<<<nbN, 256>>>(N);
    k_scan1<<<nbSc, 1024>>>(N);
    k_scan2<<<1, 32>>>(nbSc, N);
    k_scan3<<<nbSc, 1024>>>(N);
    k_scatter<<<nbE, 256>>>(ei, ew, E, N);

    // layers: hin = -1 (x) for layer 0, then alternate hA(0)/hB(1)
    int insel = -1;
    for (int l = 0; l < L; l++) {
        k_agg<<<nbAg, 256>>>(x, insel, N);
        int outsel = l & 1;               // l=0 -> hA, l=1 -> hB, l=2 -> hA
        k_gemm<<<nbGm, 256>>>(0, Wp + (size_t)l * DD * DD, bp + (size_t)l * DD, outsel, 0);
        k_gemm<<<nbGm, 256>>>(1, Wn + (size_t)l * DD * DD, bn + (size_t)l * DD, outsel, 1);
        insel = outsel;
    }

    // pool + layernorm
    k_pool<<<nbPl, 128>>>(insel, batch, N, G);
    k_ln<<<G, 128>>>(gamma, beta, (float*)d_out);
}